// round 14
// baseline (speedup 1.0000x reference)
#include <cuda_runtime.h>
#include <math.h>

#define HN   256
#define CINN 39
#define BN   128
#define SEQN 200
#define TN   1000
#define ON   61

typedef unsigned long long ull;

// packed 2xfp32 add, per-lane round-to-nearest: bit-identical to two __fadd_rn
__device__ __forceinline__ ull addf32x2(ull a, ull b) {
    ull r;
    asm("add.rn.f32x2 %0, %1, %2;" : "=l"(r) : "l"(a), "l"(b));
    return r;
}

// ---------------- scratch (device globals; no allocation allowed) ----------------
__device__ float g_Xp[2][SEQN][BN][HN];                    // input projection + bi (NOT br)
__device__ __align__(16) float g_WrT[2][257][HN];          // WrT[d][i][h]; row 256 = zeros
__device__ float g_block[SEQN][BN][2 * HN];                // 5-step block averages
__device__ float g_y[SEQN][BN][ON];                        // output-head values
__device__ float4 g_WoutT[128][64];                        // W_out k-major; o=61..63 zero

// ---------------- 1) input projection ----------------
__global__ void __launch_bounds__(256) proj_kernel(
    const float* __restrict__ x,
    const float* __restrict__ Wi_fw, const float* __restrict__ bi_fw,
    const float* __restrict__ Wi_bw, const float* __restrict__ bi_bw)
{
    int blk = blockIdx.x;          // 0..399
    int d = blk & 1;
    int f = blk >> 1;
    const float* Wi = d ? Wi_bw : Wi_fw;
    const float* bi = d ? bi_bw : bi_fw;
    int h = threadIdx.x;

    __shared__ float xs[BN][CINN + 1];
    for (int i = h; i < BN * CINN; i += blockDim.x) {
        int b = i / CINN, c = i % CINN;
        xs[b][c] = x[(b * SEQN + f) * CINN + c];
    }
    __syncthreads();

    float w[CINN];
#pragma unroll
    for (int c = 0; c < CINN; c++) w[c] = Wi[h * CINN + c];
    float bias = bi[h];

    for (int b = 0; b < BN; b += 4) {
        float s0 = 0.0f, s1 = 0.0f, s2 = 0.0f, s3 = 0.0f;
#pragma unroll
        for (int c = 0; c < CINN; c++) {
            float wc = w[c];
            s0 = __fmaf_rn(xs[b + 0][c], wc, s0);
            s1 = __fmaf_rn(xs[b + 1][c], wc, s1);
            s2 = __fmaf_rn(xs[b + 2][c], wc, s2);
            s3 = __fmaf_rn(xs[b + 3][c], wc, s3);
        }
        g_Xp[d][f][b + 0][h] = __fadd_rn(s0, bias);
        g_Xp[d][f][b + 1][h] = __fadd_rn(s1, bias);
        g_Xp[d][f][b + 2][h] = __fadd_rn(s2, bias);
        g_Xp[d][f][b + 3][h] = __fadd_rn(s3, bias);
    }
}

// ---------------- 2) transpose Wr (+1 zero pad row) ----------------
__global__ void transpose_kernel(const float* __restrict__ Wr_fw, const float* __restrict__ Wr_bw)
{
    int idx = blockIdx.x * blockDim.x + threadIdx.x;
    int total = 2 * 257 * HN;
    if (idx >= total) return;
    int d = idx / (257 * HN);
    int r = idx % (257 * HN);
    int i = r / HN;
    int h = r % HN;
    const float* Wr = d ? Wr_bw : Wr_fw;
    g_WrT[d][i][h] = (i < HN) ? Wr[h * HN + i] : 0.0f;
}

// ---------------- 2b) transpose W_out into k-major float4 layout ----------------
__global__ void outT_kernel(const float* __restrict__ W_out)
{
    int idx = blockIdx.x * blockDim.x + threadIdx.x;   // over 128*64
    if (idx >= 128 * 64) return;
    int kq = idx >> 6, oo = idx & 63;
    const float4* W4 = (const float4*)W_out;           // [61][128] float4
    g_WoutT[kq][oo] = (oo < ON) ? __ldg(W4 + oo * 128 + kq)
                                : make_float4(0.f, 0.f, 0.f, 0.f);
}

// ---------------- 3) recurrence: 256 CTAs x 128 thr; 2 neurons/thread; ONE barrier/step ----
// After the mask-exchange barrier each warp expands the full spike mask into its OWN list
// copy via __fns (lane p -> p-th set bit), so list reads need only __syncwarp.
__global__ void __launch_bounds__(128, 2) recur_kernel(
    const float* __restrict__ tau_m_fw, const float* __restrict__ tau_adp_fw,
    const float* __restrict__ tau_m_bw, const float* __restrict__ tau_adp_bw,
    const float* __restrict__ br_fw,   const float* __restrict__ br_bw)
{
    int d = blockIdx.x & 1;
    int b = blockIdx.x >> 1;
    int tid = threadIdx.x;             // 0..127
    int warp = tid >> 5, lane = tid & 31;
    int n0 = 2 * tid;                  // even neuron
    int n1 = n0 + 1;                   // odd neuron

    const float* tm = d ? tau_m_bw : tau_m_fw;
    const float* ta = d ? tau_adp_bw : tau_adp_fw;
    const float* brp = d ? br_bw : br_fw;
    float alpha0 = (float)exp((double)__fdiv_rn(-1.0f, tm[n0]));
    float alpha1 = (float)exp((double)__fdiv_rn(-1.0f, tm[n1]));
    float ro0    = (float)exp((double)__fdiv_rn(-1.0f, ta[n0]));
    float ro1    = (float)exp((double)__fdiv_rn(-1.0f, ta[n1]));
    float oma0   = __fsub_rn(1.0f, alpha0), oma1 = __fsub_rn(1.0f, alpha1);
    float omro0  = __fsub_rn(1.0f, ro0),    omro1 = __fsub_rn(1.0f, ro1);
    float br0    = brp[n0], br1 = brp[n1];

    const float* Wcol = &g_WrT[d][0][0] + n0;   // column base for this thread's neuron pair

    float mem0 = 0.0f, spk0 = 0.0f, badp0 = 0.01f, bsum0 = 0.0f, inp0 = 0.0f;
    float mem1 = 0.0f, spk1 = 0.0f, badp1 = 0.01f, bsum1 = 0.0f, inp1 = 0.0f;

    __shared__ __align__(16) unsigned smask[8];     // [warp][even/odd] interleaved masks
    __shared__ __align__(16) int slist[4][272];     // per-warp private full-list copies

    for (int t = 0; t < TN; t++) {
        int tm5 = t % 5;
        bool reload = d ? (t == 0 || tm5 == 1) : (tm5 == 0);
        if (reload) {
            int f = d ? ((200 - (t + 4) / 5) % 200) : (t / 5);
            inp0 = g_Xp[d][f][b][n0];
            inp1 = g_Xp[d][f][b][n1];
        }

        // ---- exchange spike masks (ONLY cross-warp dependency) ----
        bool s0 = (spk0 != 0.0f), s1 = (spk1 != 0.0f);
        unsigned m0 = __ballot_sync(0xffffffffu, s0);
        unsigned m1 = __ballot_sync(0xffffffffu, s1);
        if (lane == 0) { smask[warp * 2] = m0; smask[warp * 2 + 1] = m1; }
        __syncthreads();   // S1: masks visible; also fences prior-step private-list reads

        uint4 ma = *(const uint4*)smask;          // warps 0,1 (even/odd pairs)
        uint4 mb = *(const uint4*)(smask + 4);    // warps 2,3
        unsigned wd[8] = {ma.x, ma.y, ma.z, ma.w, mb.x, mb.y, mb.z, mb.w};
        int cnt = 0;
#pragma unroll
        for (int j = 0; j < 8; j++) cnt += __popc(wd[j]);
        int cnt_pad = (cnt + 15) & ~15;

        // ---- warp-private list expansion: lane pos computes pos-th active neuron ----
        // word j holds mask for neurons {2*(32*(j/2)+l) + (j&1)} = neuron order matches
        // ascending (warp-major, then even/odd interleave?) -- NO: to keep EXACT ascending
        // neuron order we must interleave even/odd per lane. Neuron index for word pair
        // (even m0, odd m1) of warp w, lane l: 64*w + 2*l (+1). Ascending global order =
        // for w: for l: [even, odd]. So the flattened bitset is built lane-major with
        // 2 bits per lane: bit (64*w + 2*l + e) = word (2*w + e) bit l.
        int* wlist = slist[warp];
        for (int pos = lane; pos < cnt_pad; pos += 32) {
            int p = pos;
            int idx = 256;             // zero-row sentinel when pos >= cnt
            int done = 0;
#pragma unroll
            for (int w = 0; w < 4; w++) {
                // neurons 64w..64w+63: interleave of wd[2w] (even) and wd[2w+1] (odd)
                unsigned me = wd[2 * w], mo = wd[2 * w + 1];
                int c = __popc(me) + __popc(mo);
                if (!done && p < c) {
                    // find p-th set bit of the interleaved 64-bit mask
                    // build interleaved low/high 32-bit words on the fly
                    ull inter = 0ull;
                    // interleave: bit 2l from me, bit 2l+1 from mo
                    unsigned e = me, o = mo;
                    // expand each to even/odd bit positions (bit twiddle, 64-bit)
                    ull ee = e, oo = o;
                    ee = (ee | (ee << 16)) & 0x0000FFFF0000FFFFull;
                    ee = (ee | (ee << 8))  & 0x00FF00FF00FF00FFull;
                    ee = (ee | (ee << 4))  & 0x0F0F0F0F0F0F0F0Full;
                    ee = (ee | (ee << 2))  & 0x3333333333333333ull;
                    ee = (ee | (ee << 1))  & 0x5555555555555555ull;
                    oo = (oo | (oo << 16)) & 0x0000FFFF0000FFFFull;
                    oo = (oo | (oo << 8))  & 0x00FF00FF00FF00FFull;
                    oo = (oo | (oo << 4))  & 0x0F0F0F0F0F0F0F0Full;
                    oo = (oo | (oo << 2))  & 0x3333333333333333ull;
                    oo = (oo | (oo << 1))  & 0x5555555555555555ull;
                    inter = ee | (oo << 1);
                    unsigned lo = (unsigned)(inter & 0xffffffffull);
                    unsigned hi = (unsigned)(inter >> 32);
                    int clo = __popc(lo);
                    int bit;
                    if (p < clo) bit = __fns(lo, 0, p + 1);
                    else         bit = 32 + __fns(hi, 0, p - clo + 1);
                    idx = 64 * w + bit;
                    done = 1;
                }
                if (!done) p -= c;
            }
            wlist[pos] = idx;
        }
        __syncwarp();      // own-list visible to own warp; no block barrier needed

        // ---- gather: 16-deep batches from OWN list copy (R8 structure) ----
        ull rsum = 0ull;   // lanes: (+0.0f, +0.0f)
        for (int k = 0; k < cnt_pad; k += 16) {
            int4 ia = *(const int4*)(wlist + k);
            int4 ib = *(const int4*)(wlist + k + 4);
            int4 ic = *(const int4*)(wlist + k + 8);
            int4 id = *(const int4*)(wlist + k + 12);
            ull v0  = __ldg((const ull*)(Wcol + ia.x * HN));
            ull v1  = __ldg((const ull*)(Wcol + ia.y * HN));
            ull v2  = __ldg((const ull*)(Wcol + ia.z * HN));
            ull v3  = __ldg((const ull*)(Wcol + ia.w * HN));
            ull v4  = __ldg((const ull*)(Wcol + ib.x * HN));
            ull v5  = __ldg((const ull*)(Wcol + ib.y * HN));
            ull v6  = __ldg((const ull*)(Wcol + ib.z * HN));
            ull v7  = __ldg((const ull*)(Wcol + ib.w * HN));
            ull v8  = __ldg((const ull*)(Wcol + ic.x * HN));
            ull v9  = __ldg((const ull*)(Wcol + ic.y * HN));
            ull v10 = __ldg((const ull*)(Wcol + ic.z * HN));
            ull v11 = __ldg((const ull*)(Wcol + ic.w * HN));
            ull v12 = __ldg((const ull*)(Wcol + id.x * HN));
            ull v13 = __ldg((const ull*)(Wcol + id.y * HN));
            ull v14 = __ldg((const ull*)(Wcol + id.z * HN));
            ull v15 = __ldg((const ull*)(Wcol + id.w * HN));
            rsum = addf32x2(rsum, v0);  rsum = addf32x2(rsum, v1);
            rsum = addf32x2(rsum, v2);  rsum = addf32x2(rsum, v3);
            rsum = addf32x2(rsum, v4);  rsum = addf32x2(rsum, v5);
            rsum = addf32x2(rsum, v6);  rsum = addf32x2(rsum, v7);
            rsum = addf32x2(rsum, v8);  rsum = addf32x2(rsum, v9);
            rsum = addf32x2(rsum, v10); rsum = addf32x2(rsum, v11);
            rsum = addf32x2(rsum, v12); rsum = addf32x2(rsum, v13);
            rsum = addf32x2(rsum, v14); rsum = addf32x2(rsum, v15);
        }
        float rs0 = __uint_as_float((unsigned)(rsum & 0xffffffffull));
        float rs1 = __uint_as_float((unsigned)(rsum >> 32));

        // ---- adaptive-LIF x2; exact JAX association, NO FMA contraction ----
        {
            float din = __fadd_rn(__fadd_rn(inp0, rs0), br0);
            badp0 = __fadd_rn(__fmul_rn(ro0, badp0), __fmul_rn(omro0, spk0));
            float Bth = __fadd_rn(0.01f, __fmul_rn(1.8f, badp0));
            mem0 = __fsub_rn(__fadd_rn(__fmul_rn(mem0, alpha0), __fmul_rn(oma0, din)),
                             __fmul_rn(Bth, spk0));
            spk0 = (__fsub_rn(mem0, Bth) > 0.0f) ? 1.0f : 0.0f;
            bsum0 = __fadd_rn(bsum0, spk0);
        }
        {
            float din = __fadd_rn(__fadd_rn(inp1, rs1), br1);
            badp1 = __fadd_rn(__fmul_rn(ro1, badp1), __fmul_rn(omro1, spk1));
            float Bth = __fadd_rn(0.01f, __fmul_rn(1.8f, badp1));
            mem1 = __fsub_rn(__fadd_rn(__fmul_rn(mem1, alpha1), __fmul_rn(oma1, din)),
                             __fmul_rn(Bth, spk1));
            spk1 = (__fsub_rn(mem1, Bth) > 0.0f) ? 1.0f : 0.0f;
            bsum1 = __fadd_rn(bsum1, spk1);
        }

        if (tm5 == 4) {
            int s = d ? (199 - t / 5) : (t / 5);
            g_block[s][b][d * HN + n0] = __fdiv_rn(bsum0, 5.0f);
            g_block[s][b][d * HN + n1] = __fdiv_rn(bsum1, 5.0f);
            bsum0 = 0.0f; bsum1 = 0.0f;
        }
    }
}

// ---------------- 4) output GEMM; x tile in smem (32KB), W via k-major L1 path ----------------
#define OUTMM_SMEM (16 * 128 * 16)
__global__ void __launch_bounds__(256) outmm_kernel(const float* __restrict__ b_out)
{
    extern __shared__ char sm_raw[];
    float4* xs4 = (float4*)sm_raw;                  // [16][128]

    int bt = blockIdx.x & 7;
    int s  = blockIdx.x >> 3;
    int tid = threadIdx.x;
    int o  = tid & 63;
    int bq = tid >> 6;      // 0..3 -> batches {bq, bq+4, bq+8, bq+12}

    const float4* gb4 = (const float4*)&g_block[s][bt * 16][0];
    for (int i = tid; i < 16 * 128; i += 256) xs4[i] = gb4[i];
    __syncthreads();

    float a0 = 0.f, a1 = 0.f, a2 = 0.f, a3 = 0.f;
    const float4* x0 = xs4 + (bq + 0) * 128;
    const float4* x1 = xs4 + (bq + 4) * 128;
    const float4* x2 = xs4 + (bq + 8) * 128;
    const float4* x3 = xs4 + (bq + 12) * 128;
#pragma unroll 4
    for (int kq = 0; kq < 128; kq++) {
        float4 wv = __ldg(&g_WoutT[kq][o]);    // lanes: contiguous 512B, L1-hot
        float4 v0 = x0[kq], v1 = x1[kq], v2 = x2[kq], v3 = x3[kq];
        a0 = __fmaf_rn(v0.x, wv.x, a0); a0 = __fmaf_rn(v0.y, wv.y, a0);
        a0 = __fmaf_rn(v0.z, wv.z, a0); a0 = __fmaf_rn(v0.w, wv.w, a0);
        a1 = __fmaf_rn(v1.x, wv.x, a1); a1 = __fmaf_rn(v1.y, wv.y, a1);
        a1 = __fmaf_rn(v1.z, wv.z, a1); a1 = __fmaf_rn(v1.w, wv.w, a1);
        a2 = __fmaf_rn(v2.x, wv.x, a2); a2 = __fmaf_rn(v2.y, wv.y, a2);
        a2 = __fmaf_rn(v2.z, wv.z, a2); a2 = __fmaf_rn(v2.w, wv.w, a2);
        a3 = __fmaf_rn(v3.x, wv.x, a3); a3 = __fmaf_rn(v3.y, wv.y, a3);
        a3 = __fmaf_rn(v3.z, wv.z, a3); a3 = __fmaf_rn(v3.w, wv.w, a3);
    }
    if (o < ON) {
        float bo = b_out[o];
        int bb = bt * 16 + bq;
        g_y[s][bb + 0][o]  = __fadd_rn(a0, bo);
        g_y[s][bb + 4][o]  = __fadd_rn(a1, bo);
        g_y[s][bb + 8][o]  = __fadd_rn(a2, bo);
        g_y[s][bb + 12][o] = __fadd_rn(a3, bo);
    }
}

// ---------------- 5) leaky-integrator scan over s ----------------
__global__ void scan_kernel(const float* __restrict__ tau_m_out)
{
    int idx = blockIdx.x * blockDim.x + threadIdx.x;
    if (idx >= BN * ON) return;
    int b = idx / ON, o = idx % ON;
    float a = (float)exp((double)__fdiv_rn(-1.0f, tau_m_out[o]));
    float omA = __fsub_rn(1.0f, a);
    float mem = 0.0f;
    for (int s = 0; s < SEQN; s++) {
        mem = __fadd_rn(__fmul_rn(mem, a), __fmul_rn(omA, g_y[s][b][o]));
        g_y[s][b][o] = mem;
    }
}

// ---------------- 6) log_softmax per (s,b) row ----------------
__global__ void __launch_bounds__(256) softmax_kernel(float* __restrict__ out)
{
    int row = blockIdx.x * (blockDim.x >> 5) + (threadIdx.x >> 5);
    if (row >= SEQN * BN) return;
    int lane = threadIdx.x & 31;
    const float* yr = &g_y[0][0][0] + row * ON;

    float v0 = (lane < ON)      ? yr[lane]      : -1e30f;
    float v1 = (lane + 32 < ON) ? yr[lane + 32] : -1e30f;
    float mx = fmaxf(v0, v1);
#pragma unroll
    for (int off = 16; off; off >>= 1) mx = fmaxf(mx, __shfl_xor_sync(0xffffffffu, mx, off));
    float e = ((lane < ON) ? expf(__fsub_rn(v0, mx)) : 0.0f)
            + ((lane + 32 < ON) ? expf(__fsub_rn(v1, mx)) : 0.0f);
#pragma unroll
    for (int off = 16; off; off >>= 1) e += __shfl_xor_sync(0xffffffffu, e, off);
    float lse = __fadd_rn(mx, logf(e));
    if (lane < ON)      out[row * ON + lane]      = __fsub_rn(v0, lse);
    if (lane + 32 < ON) out[row * ON + lane + 32] = __fsub_rn(v1, lse);
}

// ---------------- host launcher ----------------
extern "C" void kernel_launch(void* const* d_in, const int* in_sizes, int n_in,
                              void* d_out, int out_size)
{
    const float* x         = (const float*)d_in[0];
    const float* Wi_fw     = (const float*)d_in[1];
    const float* bi_fw     = (const float*)d_in[2];
    const float* Wr_fw     = (const float*)d_in[3];
    const float* br_fw     = (const float*)d_in[4];
    const float* tau_m_fw  = (const float*)d_in[5];
    const float* tau_adp_fw= (const float*)d_in[6];
    const float* Wi_bw     = (const float*)d_in[7];
    const float* bi_bw     = (const float*)d_in[8];
    const float* Wr_bw     = (const float*)d_in[9];
    const float* br_bw     = (const float*)d_in[10];
    const float* tau_m_bw  = (const float*)d_in[11];
    const float* tau_adp_bw= (const float*)d_in[12];
    const float* W_out     = (const float*)d_in[13];
    const float* b_out     = (const float*)d_in[14];
    const float* tau_m_out = (const float*)d_in[15];

    static int configured = 0;
    if (!configured) {
        cudaFuncSetAttribute(outmm_kernel, cudaFuncAttributeMaxDynamicSharedMemorySize, OUTMM_SMEM);
        cudaFuncSetAttribute(recur_kernel, cudaFuncAttributePreferredSharedMemoryCarveout, 0); // max L1
        configured = 1;
    }

    proj_kernel<<<2 * SEQN, 256>>>(x, Wi_fw, bi_fw, Wi_bw, bi_bw);                 // 1
    transpose_kernel<<<(2 * 257 * HN + 255) / 256, 256>>>(Wr_fw, Wr_bw);           // 2
    outT_kernel<<<(128 * 64 + 255) / 256, 256>>>(W_out);                           // 3
    recur_kernel<<<2 * BN, 128>>>(tau_m_fw, tau_adp_fw, tau_m_bw, tau_adp_bw,      // 4 (ncu slot)
                                  br_fw, br_bw);
    outmm_kernel<<<SEQN * 8, 256, OUTMM_SMEM>>>(b_out);                            // 5
    scan_kernel<<<(BN * ON + 255) / 256, 256>>>(tau_m_out);                        // 6
    softmax_kernel<<<(SEQN * BN + 7) / 8, 256>>>((float*)d_out);                   // 7
}

// round 16
// speedup vs baseline: 4.9668x; 4.9668x over previous
#include <cuda_runtime.h>
#include <math.h>

#define HN   256
#define CINN 39
#define BN   128
#define SEQN 200
#define TN   1000
#define ON   61

typedef unsigned long long ull;

// packed 2xfp32 add, per-lane round-to-nearest: bit-identical to two __fadd_rn
__device__ __forceinline__ ull addf32x2(ull a, ull b) {
    ull r;
    asm("add.rn.f32x2 %0, %1, %2;" : "=l"(r) : "l"(a), "l"(b));
    return r;
}

// ---------------- scratch (device globals; no allocation allowed) ----------------
__device__ float g_Xp[2][SEQN][BN][HN];                    // input projection + bi (NOT br)
__device__ __align__(16) float g_WrT[2][257][HN];          // WrT[d][i][h]; row 256 = zeros
__device__ float g_block[SEQN][BN][2 * HN];                // 5-step block averages
__device__ float g_y[SEQN][BN][ON];                        // output-head values
__device__ float4 g_WoutT[128][64];                        // W_out k-major; o=61..63 zero

// ---------------- 1) input projection ----------------
__global__ void __launch_bounds__(256) proj_kernel(
    const float* __restrict__ x,
    const float* __restrict__ Wi_fw, const float* __restrict__ bi_fw,
    const float* __restrict__ Wi_bw, const float* __restrict__ bi_bw)
{
    int blk = blockIdx.x;          // 0..399
    int d = blk & 1;
    int f = blk >> 1;
    const float* Wi = d ? Wi_bw : Wi_fw;
    const float* bi = d ? bi_bw : bi_fw;
    int h = threadIdx.x;

    __shared__ float xs[BN][CINN + 1];
    for (int i = h; i < BN * CINN; i += blockDim.x) {
        int b = i / CINN, c = i % CINN;
        xs[b][c] = x[(b * SEQN + f) * CINN + c];
    }
    __syncthreads();

    float w[CINN];
#pragma unroll
    for (int c = 0; c < CINN; c++) w[c] = Wi[h * CINN + c];
    float bias = bi[h];

    for (int b = 0; b < BN; b += 4) {
        float s0 = 0.0f, s1 = 0.0f, s2 = 0.0f, s3 = 0.0f;
#pragma unroll
        for (int c = 0; c < CINN; c++) {
            float wc = w[c];
            s0 = __fmaf_rn(xs[b + 0][c], wc, s0);
            s1 = __fmaf_rn(xs[b + 1][c], wc, s1);
            s2 = __fmaf_rn(xs[b + 2][c], wc, s2);
            s3 = __fmaf_rn(xs[b + 3][c], wc, s3);
        }
        g_Xp[d][f][b + 0][h] = __fadd_rn(s0, bias);
        g_Xp[d][f][b + 1][h] = __fadd_rn(s1, bias);
        g_Xp[d][f][b + 2][h] = __fadd_rn(s2, bias);
        g_Xp[d][f][b + 3][h] = __fadd_rn(s3, bias);
    }
}

// ---------------- 2) transpose Wr (+1 zero pad row) ----------------
__global__ void transpose_kernel(const float* __restrict__ Wr_fw, const float* __restrict__ Wr_bw)
{
    int idx = blockIdx.x * blockDim.x + threadIdx.x;
    int total = 2 * 257 * HN;
    if (idx >= total) return;
    int d = idx / (257 * HN);
    int r = idx % (257 * HN);
    int i = r / HN;
    int h = r % HN;
    const float* Wr = d ? Wr_bw : Wr_fw;
    g_WrT[d][i][h] = (i < HN) ? Wr[h * HN + i] : 0.0f;
}

// ---------------- 2b) transpose W_out into k-major float4 layout ----------------
__global__ void outT_kernel(const float* __restrict__ W_out)
{
    int idx = blockIdx.x * blockDim.x + threadIdx.x;   // over 128*64
    if (idx >= 128 * 64) return;
    int kq = idx >> 6, oo = idx & 63;
    const float4* W4 = (const float4*)W_out;           // [61][128] float4
    g_WoutT[kq][oo] = (oo < ON) ? __ldg(W4 + oo * 128 + kq)
                                : make_float4(0.f, 0.f, 0.f, 0.f);
}

// ---------------- 3) recurrence: R8 structure + byte-offset slist + frame prefetch ----------
// 256 CTAs x 128 thr; 2 neurons/thread; bid & bid+148 share an SM with equal parity ->
// same direction -> one WrT working set per SM L1; 2 CTAs/SM mutually hide stalls.
__global__ void __launch_bounds__(128, 2) recur_kernel(
    const float* __restrict__ tau_m_fw, const float* __restrict__ tau_adp_fw,
    const float* __restrict__ tau_m_bw, const float* __restrict__ tau_adp_bw,
    const float* __restrict__ br_fw,   const float* __restrict__ br_bw)
{
    int d = blockIdx.x & 1;
    int b = blockIdx.x >> 1;
    int tid = threadIdx.x;             // 0..127
    int warp = tid >> 5, lane = tid & 31;
    int n0 = 2 * tid;                  // even neuron
    int n1 = n0 + 1;                   // odd neuron

    const float* tm = d ? tau_m_bw : tau_m_fw;
    const float* ta = d ? tau_adp_bw : tau_adp_fw;
    const float* brp = d ? br_bw : br_fw;
    float alpha0 = (float)exp((double)__fdiv_rn(-1.0f, tm[n0]));
    float alpha1 = (float)exp((double)__fdiv_rn(-1.0f, tm[n1]));
    float ro0    = (float)exp((double)__fdiv_rn(-1.0f, ta[n0]));
    float ro1    = (float)exp((double)__fdiv_rn(-1.0f, ta[n1]));
    float oma0   = __fsub_rn(1.0f, alpha0), oma1 = __fsub_rn(1.0f, alpha1);
    float omro0  = __fsub_rn(1.0f, ro0),    omro1 = __fsub_rn(1.0f, ro1);
    float br0    = brp[n0], br1 = brp[n1];

    const char* Wcol = (const char*)(&g_WrT[d][0][0] + n0);  // column base (byte addressing)

    float mem0 = 0.0f, spk0 = 0.0f, badp0 = 0.01f, bsum0 = 0.0f;
    float mem1 = 0.0f, spk1 = 0.0f, badp1 = 0.01f, bsum1 = 0.0f;

    // ---- initial frame (f=0 for both dirs) + prefetch of the following frame ----
    float inp0 = g_Xp[d][0][b][n0];
    float inp1 = g_Xp[d][0][b][n1];
    int fnext = d ? 199 : 1;
    float pin0 = __ldg(&g_Xp[d][fnext][b][n0]);
    float pin1 = __ldg(&g_Xp[d][fnext][b][n1]);

    __shared__ __align__(16) unsigned smask[8];     // [warp][even/odd]
    __shared__ __align__(16) int slist[256];        // BYTE offsets (neuron << 10)

    unsigned lanelt = (lane == 0) ? 0u : (0xffffffffu >> (32 - lane));

    for (int t = 0; t < TN; t++) {
        int tm5 = t % 5;
        // consume prefetched frame; immediately prefetch the one after (~5 steps of slack)
        bool reload = d ? (tm5 == 1) : (t > 0 && tm5 == 0);
        if (reload) {
            inp0 = pin0;
            inp1 = pin1;
            int ff;
            if (d) {               // current frame 200-(t+4)/5; next reload uses f-1
                int f = 200 - (t + 4) / 5;     // t%5==1 -> exact
                ff = (f > 0) ? (f - 1) : 0;    // clamp (last frame value unused)
            } else {
                int f = t / 5;
                ff = (f < 199) ? (f + 1) : 199;
            }
            pin0 = __ldg(&g_Xp[d][ff][b][n0]);
            pin1 = __ldg(&g_Xp[d][ff][b][n1]);
        }

        // ---- build active-neuron list (ascending neuron index; byte offsets) ----
        bool s0 = (spk0 != 0.0f), s1 = (spk1 != 0.0f);
        unsigned m0 = __ballot_sync(0xffffffffu, s0);
        unsigned m1 = __ballot_sync(0xffffffffu, s1);
        if (lane == 0) { smask[warp * 2] = m0; smask[warp * 2 + 1] = m1; }
        __syncthreads();   // S1: masks visible; fences prior-step slist reads vs writes

        uint4 ma = *(const uint4*)smask;          // warps 0,1
        uint4 mb = *(const uint4*)(smask + 4);    // warps 2,3
        int pw0 = __popc(ma.x) + __popc(ma.y);
        int pw1 = __popc(ma.z) + __popc(ma.w);
        int pw2 = __popc(mb.x) + __popc(mb.y);
        int pw3 = __popc(mb.z) + __popc(mb.w);
        int cnt = pw0 + pw1 + pw2 + pw3;
        int base = 0;
        if (warp > 0) base += pw0;
        if (warp > 1) base += pw1;
        if (warp > 2) base += pw2;

        int p0 = base + __popc(m0 & lanelt) + __popc(m1 & lanelt);
        if (s0) slist[p0] = n0 << 10;
        if (s1) slist[p0 + (s0 ? 1 : 0)] = n1 << 10;
        int cnt_pad = (cnt + 15) & ~15;
        if (tid < cnt_pad - cnt) slist[cnt + tid] = 256 << 10;   // zero-row sentinel
        __syncthreads();   // S2: list visible

        // ---- gather: 16-deep batches, byte-offset addressing (no per-load IMAD) ----
        ull rsum = 0ull;   // lanes: (+0.0f, +0.0f)
        for (int k = 0; k < cnt_pad; k += 16) {
            int4 ia = *(const int4*)(slist + k);
            int4 ib = *(const int4*)(slist + k + 4);
            int4 ic = *(const int4*)(slist + k + 8);
            int4 id = *(const int4*)(slist + k + 12);
            ull v0  = __ldg((const ull*)(Wcol + ia.x));
            ull v1  = __ldg((const ull*)(Wcol + ia.y));
            ull v2  = __ldg((const ull*)(Wcol + ia.z));
            ull v3  = __ldg((const ull*)(Wcol + ia.w));
            ull v4  = __ldg((const ull*)(Wcol + ib.x));
            ull v5  = __ldg((const ull*)(Wcol + ib.y));
            ull v6  = __ldg((const ull*)(Wcol + ib.z));
            ull v7  = __ldg((const ull*)(Wcol + ib.w));
            ull v8  = __ldg((const ull*)(Wcol + ic.x));
            ull v9  = __ldg((const ull*)(Wcol + ic.y));
            ull v10 = __ldg((const ull*)(Wcol + ic.z));
            ull v11 = __ldg((const ull*)(Wcol + ic.w));
            ull v12 = __ldg((const ull*)(Wcol + id.x));
            ull v13 = __ldg((const ull*)(Wcol + id.y));
            ull v14 = __ldg((const ull*)(Wcol + id.z));
            ull v15 = __ldg((const ull*)(Wcol + id.w));
            rsum = addf32x2(rsum, v0);  rsum = addf32x2(rsum, v1);
            rsum = addf32x2(rsum, v2);  rsum = addf32x2(rsum, v3);
            rsum = addf32x2(rsum, v4);  rsum = addf32x2(rsum, v5);
            rsum = addf32x2(rsum, v6);  rsum = addf32x2(rsum, v7);
            rsum = addf32x2(rsum, v8);  rsum = addf32x2(rsum, v9);
            rsum = addf32x2(rsum, v10); rsum = addf32x2(rsum, v11);
            rsum = addf32x2(rsum, v12); rsum = addf32x2(rsum, v13);
            rsum = addf32x2(rsum, v14); rsum = addf32x2(rsum, v15);
        }
        float rs0 = __uint_as_float((unsigned)(rsum & 0xffffffffull));
        float rs1 = __uint_as_float((unsigned)(rsum >> 32));

        // ---- adaptive-LIF x2; exact JAX association, NO FMA contraction ----
        {
            float din = __fadd_rn(__fadd_rn(inp0, rs0), br0);
            badp0 = __fadd_rn(__fmul_rn(ro0, badp0), __fmul_rn(omro0, spk0));
            float Bth = __fadd_rn(0.01f, __fmul_rn(1.8f, badp0));
            mem0 = __fsub_rn(__fadd_rn(__fmul_rn(mem0, alpha0), __fmul_rn(oma0, din)),
                             __fmul_rn(Bth, spk0));
            spk0 = (__fsub_rn(mem0, Bth) > 0.0f) ? 1.0f : 0.0f;
            bsum0 = __fadd_rn(bsum0, spk0);
        }
        {
            float din = __fadd_rn(__fadd_rn(inp1, rs1), br1);
            badp1 = __fadd_rn(__fmul_rn(ro1, badp1), __fmul_rn(omro1, spk1));
            float Bth = __fadd_rn(0.01f, __fmul_rn(1.8f, badp1));
            mem1 = __fsub_rn(__fadd_rn(__fmul_rn(mem1, alpha1), __fmul_rn(oma1, din)),
                             __fmul_rn(Bth, spk1));
            spk1 = (__fsub_rn(mem1, Bth) > 0.0f) ? 1.0f : 0.0f;
            bsum1 = __fadd_rn(bsum1, spk1);
        }

        if (tm5 == 4) {
            int s = d ? (199 - t / 5) : (t / 5);
            g_block[s][b][d * HN + n0] = __fdiv_rn(bsum0, 5.0f);
            g_block[s][b][d * HN + n1] = __fdiv_rn(bsum1, 5.0f);
            bsum0 = 0.0f; bsum1 = 0.0f;
        }
    }
}

// ---------------- 4) output GEMM; x tile in smem (32KB), W via k-major L1 path ----------------
#define OUTMM_SMEM (16 * 128 * 16)
__global__ void __launch_bounds__(256) outmm_kernel(const float* __restrict__ b_out)
{
    extern __shared__ char sm_raw[];
    float4* xs4 = (float4*)sm_raw;                  // [16][128]

    int bt = blockIdx.x & 7;
    int s  = blockIdx.x >> 3;
    int tid = threadIdx.x;
    int o  = tid & 63;
    int bq = tid >> 6;      // 0..3 -> batches {bq, bq+4, bq+8, bq+12}

    const float4* gb4 = (const float4*)&g_block[s][bt * 16][0];
    for (int i = tid; i < 16 * 128; i += 256) xs4[i] = gb4[i];
    __syncthreads();

    float a0 = 0.f, a1 = 0.f, a2 = 0.f, a3 = 0.f;
    const float4* x0 = xs4 + (bq + 0) * 128;
    const float4* x1 = xs4 + (bq + 4) * 128;
    const float4* x2 = xs4 + (bq + 8) * 128;
    const float4* x3 = xs4 + (bq + 12) * 128;
#pragma unroll 4
    for (int kq = 0; kq < 128; kq++) {
        float4 wv = __ldg(&g_WoutT[kq][o]);    // lanes: contiguous 512B, L1-hot
        float4 v0 = x0[kq], v1 = x1[kq], v2 = x2[kq], v3 = x3[kq];
        a0 = __fmaf_rn(v0.x, wv.x, a0); a0 = __fmaf_rn(v0.y, wv.y, a0);
        a0 = __fmaf_rn(v0.z, wv.z, a0); a0 = __fmaf_rn(v0.w, wv.w, a0);
        a1 = __fmaf_rn(v1.x, wv.x, a1); a1 = __fmaf_rn(v1.y, wv.y, a1);
        a1 = __fmaf_rn(v1.z, wv.z, a1); a1 = __fmaf_rn(v1.w, wv.w, a1);
        a2 = __fmaf_rn(v2.x, wv.x, a2); a2 = __fmaf_rn(v2.y, wv.y, a2);
        a2 = __fmaf_rn(v2.z, wv.z, a2); a2 = __fmaf_rn(v2.w, wv.w, a2);
        a3 = __fmaf_rn(v3.x, wv.x, a3); a3 = __fmaf_rn(v3.y, wv.y, a3);
        a3 = __fmaf_rn(v3.z, wv.z, a3); a3 = __fmaf_rn(v3.w, wv.w, a3);
    }
    if (o < ON) {
        float bo = b_out[o];
        int bb = bt * 16 + bq;
        g_y[s][bb + 0][o]  = __fadd_rn(a0, bo);
        g_y[s][bb + 4][o]  = __fadd_rn(a1, bo);
        g_y[s][bb + 8][o]  = __fadd_rn(a2, bo);
        g_y[s][bb + 12][o] = __fadd_rn(a3, bo);
    }
}

// ---------------- 5) leaky-integrator scan over s ----------------
__global__ void scan_kernel(const float* __restrict__ tau_m_out)
{
    int idx = blockIdx.x * blockDim.x + threadIdx.x;
    if (idx >= BN * ON) return;
    int b = idx / ON, o = idx % ON;
    float a = (float)exp((double)__fdiv_rn(-1.0f, tau_m_out[o]));
    float omA = __fsub_rn(1.0f, a);
    float mem = 0.0f;
    for (int s = 0; s < SEQN; s++) {
        mem = __fadd_rn(__fmul_rn(mem, a), __fmul_rn(omA, g_y[s][b][o]));
        g_y[s][b][o] = mem;
    }
}

// ---------------- 6) log_softmax per (s,b) row ----------------
__global__ void __launch_bounds__(256) softmax_kernel(float* __restrict__ out)
{
    int row = blockIdx.x * (blockDim.x >> 5) + (threadIdx.x >> 5);
    if (row >= SEQN * BN) return;
    int lane = threadIdx.x & 31;
    const float* yr = &g_y[0][0][0] + row * ON;

    float v0 = (lane < ON)      ? yr[lane]      : -1e30f;
    float v1 = (lane + 32 < ON) ? yr[lane + 32] : -1e30f;
    float mx = fmaxf(v0, v1);
#pragma unroll
    for (int off = 16; off; off >>= 1) mx = fmaxf(mx, __shfl_xor_sync(0xffffffffu, mx, off));
    float e = ((lane < ON) ? expf(__fsub_rn(v0, mx)) : 0.0f)
            + ((lane + 32 < ON) ? expf(__fsub_rn(v1, mx)) : 0.0f);
#pragma unroll
    for (int off = 16; off; off >>= 1) e += __shfl_xor_sync(0xffffffffu, e, off);
    float lse = __fadd_rn(mx, logf(e));
    if (lane < ON)      out[row * ON + lane]      = __fsub_rn(v0, lse);
    if (lane + 32 < ON) out[row * ON + lane + 32] = __fsub_rn(v1, lse);
}

// ---------------- host launcher ----------------
extern "C" void kernel_launch(void* const* d_in, const int* in_sizes, int n_in,
                              void* d_out, int out_size)
{
    const float* x         = (const float*)d_in[0];
    const float* Wi_fw     = (const float*)d_in[1];
    const float* bi_fw     = (const float*)d_in[2];
    const float* Wr_fw     = (const float*)d_in[3];
    const float* br_fw     = (const float*)d_in[4];
    const float* tau_m_fw  = (const float*)d_in[5];
    const float* tau_adp_fw= (const float*)d_in[6];
    const float* Wi_bw     = (const float*)d_in[7];
    const float* bi_bw     = (const float*)d_in[8];
    const float* Wr_bw     = (const float*)d_in[9];
    const float* br_bw     = (const float*)d_in[10];
    const float* tau_m_bw  = (const float*)d_in[11];
    const float* tau_adp_bw= (const float*)d_in[12];
    const float* W_out     = (const float*)d_in[13];
    const float* b_out     = (const float*)d_in[14];
    const float* tau_m_out = (const float*)d_in[15];

    static int configured = 0;
    if (!configured) {
        cudaFuncSetAttribute(outmm_kernel, cudaFuncAttributeMaxDynamicSharedMemorySize, OUTMM_SMEM);
        cudaFuncSetAttribute(recur_kernel, cudaFuncAttributePreferredSharedMemoryCarveout, 0); // max L1
        configured = 1;
    }

    proj_kernel<<<2 * SEQN, 256>>>(x, Wi_fw, bi_fw, Wi_bw, bi_bw);                 // 1
    transpose_kernel<<<(2 * 257 * HN + 255) / 256, 256>>>(Wr_fw, Wr_bw);           // 2
    outT_kernel<<<(128 * 64 + 255) / 256, 256>>>(W_out);                           // 3
    recur_kernel<<<2 * BN, 128>>>(tau_m_fw, tau_adp_fw, tau_m_bw, tau_adp_bw,      // 4 (ncu slot)
                                  br_fw, br_bw);
    outmm_kernel<<<SEQN * 8, 256, OUTMM_SMEM>>>(b_out);                            // 5
    scan_kernel<<<(BN * ON + 255) / 256, 256>>>(tau_m_out);                        // 6
    softmax_kernel<<<(SEQN * BN + 7) / 8, 256>>>((float*)d_out);                   // 7
}